// round 8
// baseline (speedup 1.0000x reference)
#include <cuda_runtime.h>

#define MAXE   1600000
#define MAXN   100032
#define NSLOT  4736          // 148 SMs * 32 warps (slot capacity)
#define MAXELL 4000000
#define N_IT   10            // even: final x lands in d_xa
#define BLK    1024
#define DEGBINS 1024

// ---------------- scratch (no allocations allowed) ----------------
// d_cnt / d_curs / d_sinkw / d_bins zeroed by solve's epilogue for the next
// call (zero-initialized at module load for the first call).
__device__ float  d_w[MAXE];        // exp(rewards), original edge order
__device__ float2 d_ell[MAXELL];    // warp-transposed ELL: {w, bitcast(dst)}
__device__ int    d_cnt[MAXN];      // non-sink out-degree per node
__device__ int    d_curs[MAXN];     // scatter cursors per node
__device__ float  d_sinkw[MAXN];    // sum of w over edges i->sink
__device__ float  d_xa[MAXN];
__device__ float  d_xb[MAXN];
__device__ int    d_perm[MAXN];     // nodes sorted by degree
__device__ int    d_inv[MAXN];      // inverse permutation
__device__ int    d_bins[DEGBINS];  // degree histogram / cursors
__device__ int    d_elloff[NSLOT];  // ELL base offset per slot
__device__ unsigned d_flags[256];   // per-block barrier generation flags

// ---------------- setup kernels ----------------

// rewards = -softplus(feats @ W + b); w = exp(rewards);
// count non-sink edges per src; fold sink edges into d_sinkw.
// First 256 global threads also zero the barrier flags.
__global__ void rewards_kernel(const float* __restrict__ feats,
                               const float* __restrict__ W,
                               const float* __restrict__ b,
                               const int* __restrict__ src,
                               const int* __restrict__ dst,
                               const unsigned char* __restrict__ mask,
                               float* __restrict__ out_rewards,
                               int E) {
    int e = blockIdx.x * blockDim.x + threadIdx.x;
    if (e < 256) d_flags[e] = 0;
    if (e >= E) return;
    const float4* f4 = reinterpret_cast<const float4*>(feats) + (size_t)e * 8;
    float z = __ldg(b);
#pragma unroll
    for (int i = 0; i < 8; i++) {
        float4 v = __ldg(&f4[i]);
        z = fmaf(v.x, __ldg(&W[4 * i + 0]), z);
        z = fmaf(v.y, __ldg(&W[4 * i + 1]), z);
        z = fmaf(v.z, __ldg(&W[4 * i + 2]), z);
        z = fmaf(v.w, __ldg(&W[4 * i + 3]), z);
    }
    float sp = fmaxf(z, 0.0f) + log1pf(expf(-fabsf(z)));   // stable softplus
    float r = -sp;
    out_rewards[e] = r;
    float w = expf(r);
    d_w[e] = w;
    int s = src[e];
    if (mask[dst[e]])
        atomicAdd(&d_sinkw[s], w);     // x[sink] == 1 always: fold into constant
    else
        atomicAdd(&d_cnt[s], 1);
}

// multi-block degree histogram
__global__ void hist_kernel(int n) {
    int i = blockIdx.x * blockDim.x + threadIdx.x;
    if (i >= n) return;
    atomicAdd(&d_bins[min(d_cnt[i], DEGBINS - 1)], 1);
}

// single block: exclusive scan of bins -> cursors (in place)
__global__ void binscan_kernel() {
    __shared__ int sh[DEGBINS];
    int t = threadIdx.x;
    int v = d_bins[t];
    sh[t] = v;
    __syncthreads();
    for (int off = 1; off < DEGBINS; off <<= 1) {
        int u = 0;
        if (t >= off) u = sh[t - off];
        __syncthreads();
        if (t >= off) sh[t] += u;
        __syncthreads();
    }
    d_bins[t] = sh[t] - v;   // exclusive prefix
}

// multi-block counting-sort scatter -> perm/inv
__global__ void perm_kernel(int n) {
    int i = blockIdx.x * blockDim.x + threadIdx.x;
    if (i >= n) return;
    int deg = min(d_cnt[i], DEGBINS - 1);
    int pos = atomicAdd(&d_bins[deg], 1);
    d_perm[pos] = i;
    d_inv[i] = pos;
}

// single block: slot ELL offsets. Degree-sorted => slot's warp-max degree is
// the degree of its LAST element.
__global__ void slotoff_kernel(int n) {
    __shared__ int sums[1024];
    int t = threadIdx.x;
    const int nslot_used = (n + 31) >> 5;
    const int chunk = (nslot_used + 1023) / 1024;
    const int beg = t * chunk;
    const int end = min(beg + chunk, nslot_used);
    int sum = 0;
    for (int s = beg; s < end; ++s)
        sum += 32 * d_cnt[d_perm[min(s * 32 + 31, n - 1)]];
    sums[t] = sum;
    __syncthreads();
    for (int off = 1; off < 1024; off <<= 1) {
        int u = 0;
        if (t >= off) u = sums[t - off];
        __syncthreads();
        if (t >= off) sums[t] += u;
        __syncthreads();
    }
    int prefix = (t == 0) ? 0 : sums[t - 1];
    for (int s = beg; s < end; ++s) {
        d_elloff[s] = prefix;
        prefix += 32 * d_cnt[d_perm[min(s * 32 + 31, n - 1)]];
    }
    for (int s = nslot_used + t; s < NSLOT; s += 1024) d_elloff[s] = 0;
}

// scatter non-sink edges into warp-transposed ELL
__global__ void scatter_kernel(const int* __restrict__ src,
                               const int* __restrict__ dst,
                               const unsigned char* __restrict__ mask,
                               int E) {
    int e = blockIdx.x * blockDim.x + threadIdx.x;
    if (e >= E) return;
    int d = dst[e];
    if (mask[d]) return;
    int s = src[e];
    int ip = d_inv[s];
    int slot = ip >> 5, lane = ip & 31;
    int j = atomicAdd(&d_curs[s], 1);
    d_ell[d_elloff[slot] + j * 32 + lane] = make_float2(d_w[e], __int_as_float(d));
}

// ---------------- persistent solver (synchronous Jacobi) ----------------

// Flag-array barrier (distinct addresses, parallel release/acquire). Strong
// ops bypass L1 (no CCTL.IVALL) so the ELL stays L1-resident across iters.
__device__ __forceinline__ void flag_barrier(unsigned target, int nb) {
    __syncthreads();
    if (threadIdx.x < 32) {
        if (threadIdx.x == 0)
            asm volatile("st.release.gpu.global.u32 [%0], %1;"
                         :: "l"(&d_flags[blockIdx.x]), "r"(target) : "memory");
        bool ok;
        do {
            ok = true;
            for (int f = threadIdx.x; f < nb; f += 32) {
                unsigned v;
                asm volatile("ld.acquire.gpu.global.u32 %0, [%1];"
                             : "=r"(v) : "l"(&d_flags[f]));
                ok &= (v >= target);
            }
        } while (!__all_sync(0xffffffffu, ok));
    }
    __syncthreads();
}

__global__ void __launch_bounds__(BLK, 1)
solve_kernel(const int* __restrict__ src, const int* __restrict__ dst,
             const unsigned char* __restrict__ mask,
             float* __restrict__ out_values, float* __restrict__ out_probs,
             int N, int E) {
    const int nb = gridDim.x;
    const int lane = threadIdx.x & 31;
    const int wib  = threadIdx.x >> 5;
    const int slot = wib * nb + blockIdx.x;     // interleaved, degree-balanced
    const int idx  = slot * 32 + lane;
    const int nthreads = nb * BLK;

    const bool has = (idx < N);
    int node = 0, myc = 0;
    float sc = 0.0f;
    bool sink = false;
    const float2* base = d_ell + ((slot < NSLOT) ? d_elloff[slot] : 0) + lane;
    if (has) {
        node = d_perm[idx];
        myc = d_cnt[node];
        sc = d_sinkw[node];
        sink = (mask[node] != 0);
        if (sink) myc = 0;
        d_xa[node] = sink ? 1.0f : 0.0f;   // x0 = sink mask
    }
    flag_barrier(1u, nb);

    const float* cur = d_xa;
    float* nxt = d_xb;
    const int m8 = myc & ~7;
    float acc = sink ? 1.0f : 0.0f;
    for (int it = 0; it < N_IT; ++it) {
        acc = sc;
        int j = 0;
        if (m8 > 0) {
            // software-pipelined 8-batches: while batch A's gathers are in
            // flight, batch B's loads+gathers are issued -> ~16 outstanding
            // L2 gathers per warp at steady state.
            float wv[8], xv[8];
#pragma unroll
            for (int k = 0; k < 8; ++k) {
                float2 e = __ldg(&base[(size_t)k * 32]);
                wv[k] = e.x;
                xv[k] = __ldcg(&cur[__float_as_int(e.y)]);
            }
            for (j = 8; j < m8; j += 8) {
                float wn[8], xn[8];
#pragma unroll
                for (int k = 0; k < 8; ++k) {
                    float2 e = __ldg(&base[(size_t)(j + k) * 32]);
                    wn[k] = e.x;
                    xn[k] = __ldcg(&cur[__float_as_int(e.y)]);
                }
#pragma unroll
                for (int k = 0; k < 8; ++k) acc = fmaf(wv[k], xv[k], acc);
#pragma unroll
                for (int k = 0; k < 8; ++k) { wv[k] = wn[k]; xv[k] = xn[k]; }
            }
#pragma unroll
            for (int k = 0; k < 8; ++k) acc = fmaf(wv[k], xv[k], acc);
        }
        for (j = m8; j < myc; ++j) {
            float2 ew = __ldg(&base[(size_t)j * 32]);
            acc = fmaf(ew.x, __ldcg(&cur[__float_as_int(ew.y)]), acc);
        }
        if (sink) acc = 1.0f;
        if (has) nxt[node] = acc;
        flag_barrier((unsigned)(it + 2), nb);
        const float* t = cur; cur = nxt; nxt = (float*)t;
    }
    // N_IT even -> cur == d_xa holds final x; acc holds this lane's value
    if (has) out_values[node] = sink ? 0.0f : logf(acc);

    const int tid = blockIdx.x * BLK + threadIdx.x;
    // edge probabilities: __ldg safe (x never entered L1 during the solve:
    // reads were __ldcg, stores are write-through; ~16x reuse -> high L1 hits)
    for (int e = tid; e < E; e += nthreads) {
        float xd = __ldg(&cur[dst[e]]);
        float xs = __ldg(&cur[src[e]]);
        out_probs[e] = d_w[e] * __fdividef(xd, xs);
    }

    // epilogue: zero accumulators for the next call (first call sees
    // zero-initialized globals; every call does identical work).
    for (int i = tid; i < N; i += nthreads) {
        d_cnt[i] = 0;
        d_curs[i] = 0;
        d_sinkw[i] = 0.0f;
    }
    for (int i = tid; i < DEGBINS; i += nthreads) d_bins[i] = 0;
}

// ---------------- launch ----------------

extern "C" void kernel_launch(void* const* d_in, const int* in_sizes, int n_in,
                              void* d_out, int out_size) {
    const int*   edge_index = (const int*)d_in[0];              // [2, E]
    const float* edge_feats = (const float*)d_in[1];            // [E, 32]
    const unsigned char* mask = (const unsigned char*)d_in[2];  // [N] bool
    const float* W = (const float*)d_in[3];                     // [32, 1]
    const float* b = (const float*)d_in[4];                     // [1]

    const int E = in_sizes[0] / 2;
    const int N = in_sizes[2];

    const int* src = edge_index;
    const int* dst = edge_index + E;

    float* out = (float*)d_out;
    float* out_rewards = out;          // [E]
    float* out_values  = out + E;      // [N]
    float* out_probs   = out + E + N;  // [E]

    static int nsm = 0;
    if (nsm == 0) {
        cudaDeviceGetAttribute(&nsm, cudaDevAttrMultiProcessorCount, 0);
        if (nsm <= 0) nsm = 148;
        if (nsm > 148) nsm = 148;      // NSLOT capacity (148*32 slots)
    }

    const int TB = 256;
    const int gE = (E + TB - 1) / TB;
    const int gN = (N + TB - 1) / TB;

    rewards_kernel<<<gE, TB>>>(edge_feats, W, b, src, dst, mask,
                               out_rewards, E);                         // 1
    hist_kernel<<<gN, TB>>>(N);                                         // 2
    binscan_kernel<<<1, DEGBINS>>>();                                   // 3
    perm_kernel<<<gN, TB>>>(N);                                         // 4
    slotoff_kernel<<<1, 1024>>>(N);                                     // 5
    scatter_kernel<<<gE, TB>>>(src, dst, mask, E);                      // 6
    solve_kernel<<<nsm, BLK>>>(src, dst, mask, out_values, out_probs,
                               N, E);                                   // 7
}

// round 9
// speedup vs baseline: 1.1101x; 1.1101x over previous
#include <cuda_runtime.h>

#define MAXE   1600000
#define MAXN   100032
#define NSLOT  4736          // 148 SMs * 32 warps (slot capacity)
#define MAXELL 4000000
#define N_IT   8             // even: final x lands in d_xa
#define BLK    1024
#define DEGBINS 1024

// ---------------- scratch (no allocations allowed) ----------------
// d_cnt / d_curs / d_sinkw zeroed by solve's epilogue for the next call
// (zero-initialized at module load for the first call).
__device__ float  d_w[MAXE];        // exp(rewards), original edge order
__device__ float2 d_ell[MAXELL];    // warp-transposed ELL: {w, bitcast(dst)}
__device__ int    d_cnt[MAXN];      // non-sink out-degree per node
__device__ int    d_curs[MAXN];     // scatter cursors per node
__device__ float  d_sinkw[MAXN];    // sum of w over edges i->sink
__device__ float  d_xa[MAXN];
__device__ float  d_xb[MAXN];
__device__ int    d_perm[MAXN];     // nodes sorted by degree
__device__ int    d_inv[MAXN];      // inverse permutation
__device__ int    d_elloff[NSLOT];  // ELL base offset per slot
__device__ unsigned d_flags[256];   // per-block barrier generation flags

// ---------------- setup kernels ----------------

// Warp-cooperative rewards: 4 edges per warp per step; 32 lanes read 32
// CONSECUTIVE float4s (512B coalesced). Lane l: row sub = l>>3, chunk = l&7.
// 8-lane shfl reduction -> lane ch==0 finishes the edge.
__global__ void rewards_kernel(const float* __restrict__ feats,
                               const float* __restrict__ W,
                               const float* __restrict__ b,
                               const int* __restrict__ src,
                               const int* __restrict__ dst,
                               const unsigned char* __restrict__ mask,
                               float* __restrict__ out_rewards,
                               int E) {
    const int tid = blockIdx.x * blockDim.x + threadIdx.x;
    if (tid < 256) d_flags[tid] = 0;
    const int lane = threadIdx.x & 31;
    const int gw = tid >> 5;                 // global warp id
    const int sub = lane >> 3;               // 0..3 (edge within warp's group)
    const int ch  = lane & 7;                // 0..7 (float4 chunk within row)
    const int e = gw * 4 + sub;
    if (gw * 4 >= E) return;

    float part = 0.0f;
    if (e < E) {
        float4 v = __ldg(&reinterpret_cast<const float4*>(feats)[(size_t)e * 8 + ch]);
        part = v.x * __ldg(&W[ch * 4 + 0]) + v.y * __ldg(&W[ch * 4 + 1])
             + v.z * __ldg(&W[ch * 4 + 2]) + v.w * __ldg(&W[ch * 4 + 3]);
    }
    part += __shfl_down_sync(0xffffffffu, part, 4, 8);
    part += __shfl_down_sync(0xffffffffu, part, 2, 8);
    part += __shfl_down_sync(0xffffffffu, part, 1, 8);

    if (e < E && ch == 0) {
        float z = part + __ldg(b);
        float sp = fmaxf(z, 0.0f) + log1pf(expf(-fabsf(z)));   // stable softplus
        float r = -sp;
        out_rewards[e] = r;
        float w = expf(r);
        d_w[e] = w;
        int s = src[e];
        if (mask[dst[e]])
            atomicAdd(&d_sinkw[s], w);   // x[sink] == 1 always: fold into constant
        else
            atomicAdd(&d_cnt[s], 1);
    }
}

// single block: degree counting-sort permutation (smem bins -> cheap atomics)
// + slot ELL offsets. Degree-sorted => slot's warp-max degree = degree of its
// LAST element.
__global__ void build_perm_kernel(int n) {
    __shared__ int bins[DEGBINS];
    __shared__ int curs[DEGBINS];
    int t = threadIdx.x;
    bins[t] = 0;
    __syncthreads();
    for (int i = t; i < n; i += DEGBINS)
        atomicAdd(&bins[min(d_cnt[i], DEGBINS - 1)], 1);
    __syncthreads();
    int v = bins[t];
    for (int off = 1; off < DEGBINS; off <<= 1) {       // inclusive scan
        int u = 0;
        if (t >= off) u = bins[t - off];
        __syncthreads();
        if (t >= off) bins[t] += u;
        __syncthreads();
    }
    curs[t] = bins[t] - v;   // exclusive prefix
    __syncthreads();
    for (int i = t; i < n; i += DEGBINS) {
        int deg = min(d_cnt[i], DEGBINS - 1);
        int pos = atomicAdd(&curs[deg], 1);
        d_perm[pos] = i;
        d_inv[i] = pos;
    }
    __syncthreads();
    // ---- slot offsets: elloff[s] = 32 * prefix of max-degree-in-slot ----
    const int nslot_used = (n + 31) >> 5;
    const int chunk = (nslot_used + DEGBINS - 1) / DEGBINS;
    const int beg = t * chunk;
    const int end = min(beg + chunk, nslot_used);
    int sum = 0;
    for (int s = beg; s < end; ++s)
        sum += 32 * d_cnt[d_perm[min(s * 32 + 31, n - 1)]];
    bins[t] = sum;           // reuse smem
    __syncthreads();
    for (int off = 1; off < DEGBINS; off <<= 1) {
        int u = 0;
        if (t >= off) u = bins[t - off];
        __syncthreads();
        if (t >= off) bins[t] += u;
        __syncthreads();
    }
    int prefix = (t == 0) ? 0 : bins[t - 1];
    for (int s = beg; s < end; ++s) {
        d_elloff[s] = prefix;
        prefix += 32 * d_cnt[d_perm[min(s * 32 + 31, n - 1)]];
    }
    for (int s = nslot_used + t; s < NSLOT; s += DEGBINS) d_elloff[s] = 0;
}

// scatter non-sink edges into warp-transposed ELL
__global__ void scatter_kernel(const int* __restrict__ src,
                               const int* __restrict__ dst,
                               const unsigned char* __restrict__ mask,
                               int E) {
    int e = blockIdx.x * blockDim.x + threadIdx.x;
    if (e >= E) return;
    int d = dst[e];
    if (mask[d]) return;
    int s = src[e];
    int ip = d_inv[s];
    int slot = ip >> 5, lane = ip & 31;
    int j = atomicAdd(&d_curs[s], 1);
    d_ell[d_elloff[slot] + j * 32 + lane] = make_float2(d_w[e], __int_as_float(d));
}

// ---------------- persistent solver (synchronous Jacobi) ----------------

// Flag-array barrier (distinct addresses, parallel release/acquire). Strong
// ops bypass L1 (no CCTL.IVALL) so the ELL stays L1-resident across iters.
__device__ __forceinline__ void flag_barrier(unsigned target, int nb) {
    __syncthreads();
    if (threadIdx.x < 32) {
        if (threadIdx.x == 0)
            asm volatile("st.release.gpu.global.u32 [%0], %1;"
                         :: "l"(&d_flags[blockIdx.x]), "r"(target) : "memory");
        bool ok;
        do {
            ok = true;
            for (int f = threadIdx.x; f < nb; f += 32) {
                unsigned v;
                asm volatile("ld.acquire.gpu.global.u32 %0, [%1];"
                             : "=r"(v) : "l"(&d_flags[f]));
                ok &= (v >= target);
            }
        } while (!__all_sync(0xffffffffu, ok));
    }
    __syncthreads();
}

__global__ void __launch_bounds__(BLK, 1)
solve_kernel(const int* __restrict__ src, const int* __restrict__ dst,
             const unsigned char* __restrict__ mask,
             float* __restrict__ out_values, float* __restrict__ out_probs,
             int N, int E) {
    const int nb = gridDim.x;
    const int lane = threadIdx.x & 31;
    const int wib  = threadIdx.x >> 5;
    const int slot = wib * nb + blockIdx.x;     // interleaved, degree-balanced
    const int idx  = slot * 32 + lane;
    const int nthreads = nb * BLK;

    const bool has = (idx < N);
    int node = 0, myc = 0;
    float sc = 0.0f;
    bool sink = false;
    const float2* base = d_ell + ((slot < NSLOT) ? d_elloff[slot] : 0) + lane;
    if (has) {
        node = d_perm[idx];
        myc = d_cnt[node];
        sc = d_sinkw[node];
        sink = (mask[node] != 0);
        if (sink) myc = 0;
        d_xa[node] = sink ? 1.0f : 0.0f;   // x0 = sink mask
    }
    flag_barrier(1u, nb);

    const float* cur = d_xa;
    float* nxt = d_xb;
    const int m8 = myc & ~7;
    float acc = sink ? 1.0f : 0.0f;
    for (int it = 0; it < N_IT; ++it) {
        acc = sc;
        int j = 0;
        if (m8 > 0) {
            // software-pipelined 8-batches: ~16 outstanding L2 gathers/warp
            float wv[8], xv[8];
#pragma unroll
            for (int k = 0; k < 8; ++k) {
                float2 e = __ldg(&base[(size_t)k * 32]);
                wv[k] = e.x;
                xv[k] = __ldcg(&cur[__float_as_int(e.y)]);
            }
            for (j = 8; j < m8; j += 8) {
                float wn[8], xn[8];
#pragma unroll
                for (int k = 0; k < 8; ++k) {
                    float2 e = __ldg(&base[(size_t)(j + k) * 32]);
                    wn[k] = e.x;
                    xn[k] = __ldcg(&cur[__float_as_int(e.y)]);
                }
#pragma unroll
                for (int k = 0; k < 8; ++k) acc = fmaf(wv[k], xv[k], acc);
#pragma unroll
                for (int k = 0; k < 8; ++k) { wv[k] = wn[k]; xv[k] = xn[k]; }
            }
#pragma unroll
            for (int k = 0; k < 8; ++k) acc = fmaf(wv[k], xv[k], acc);
        }
        for (j = m8; j < myc; ++j) {
            float2 ew = __ldg(&base[(size_t)j * 32]);
            acc = fmaf(ew.x, __ldcg(&cur[__float_as_int(ew.y)]), acc);
        }
        if (sink) acc = 1.0f;
        if (has) nxt[node] = acc;
        flag_barrier((unsigned)(it + 2), nb);
        const float* t = cur; cur = nxt; nxt = (float*)t;
    }
    // N_IT even -> cur == d_xa holds final x; acc holds this lane's value
    if (has) out_values[node] = sink ? 0.0f : logf(acc);

    const int tid = blockIdx.x * BLK + threadIdx.x;
    // edge probabilities: __ldg safe (x never entered L1 during the solve;
    // ~16x reuse per node -> high L1 hit rate)
    for (int e = tid; e < E; e += nthreads) {
        float xd = __ldg(&cur[dst[e]]);
        float xs = __ldg(&cur[src[e]]);
        out_probs[e] = d_w[e] * __fdividef(xd, xs);
    }

    // epilogue: zero accumulators for the next call (first call sees
    // zero-initialized globals; every call does identical work).
    for (int i = tid; i < N; i += nthreads) {
        d_cnt[i] = 0;
        d_curs[i] = 0;
        d_sinkw[i] = 0.0f;
    }
}

// ---------------- launch ----------------

extern "C" void kernel_launch(void* const* d_in, const int* in_sizes, int n_in,
                              void* d_out, int out_size) {
    const int*   edge_index = (const int*)d_in[0];              // [2, E]
    const float* edge_feats = (const float*)d_in[1];            // [E, 32]
    const unsigned char* mask = (const unsigned char*)d_in[2];  // [N] bool
    const float* W = (const float*)d_in[3];                     // [32, 1]
    const float* b = (const float*)d_in[4];                     // [1]

    const int E = in_sizes[0] / 2;
    const int N = in_sizes[2];

    const int* src = edge_index;
    const int* dst = edge_index + E;

    float* out = (float*)d_out;
    float* out_rewards = out;          // [E]
    float* out_values  = out + E;      // [N]
    float* out_probs   = out + E + N;  // [E]

    static int nsm = 0;
    if (nsm == 0) {
        cudaDeviceGetAttribute(&nsm, cudaDevAttrMultiProcessorCount, 0);
        if (nsm <= 0) nsm = 148;
        if (nsm > 148) nsm = 148;      // NSLOT capacity (148*32 slots)
    }

    const int TB = 256;
    const int gE = (E + TB - 1) / TB;
    const int nwarps = (E + 3) / 4;                    // 4 edges per warp
    const int gR = (nwarps * 32 + TB - 1) / TB;

    rewards_kernel<<<gR, TB>>>(edge_feats, W, b, src, dst, mask,
                               out_rewards, E);                         // 1
    build_perm_kernel<<<1, DEGBINS>>>(N);                               // 2
    scatter_kernel<<<gE, TB>>>(src, dst, mask, E);                      // 3
    solve_kernel<<<nsm, BLK>>>(src, dst, mask, out_values, out_probs,
                               N, E);                                   // 4
}